// round 1
// baseline (speedup 1.0000x reference)
#include <cuda_runtime.h>
#include <math.h>

#define NN 8
#define BB 64
#define TT 256
#define DIN 64
#define HH 512
#define MMd 512
#define OO 7

// ---------------- scratch (device globals; no allocation allowed) ----------------
__device__ float g_z[BB * TT * HH];          // 8.4M floats  (input-layer output, token-major [b*T+t][H])
__device__ float g_h0[2][NN * BB * HH];      // double-buffered layer-0 hidden
__device__ float g_h1[2][NN * BB * HH];      // double-buffered layer-1 hidden
__device__ float g_c0[NN * BB * HH];         // cell states (in-place safe: each elem owned by 1 thread)
__device__ float g_c1[NN * BB * HH];
__device__ float g_y[(size_t)NN * BB * TT * HH];  // 67M floats, layer-1 outputs over time

__device__ __forceinline__ float sigf(float x) { return 1.0f / (1.0f + expf(-x)); }

// ---------------- init: zero initial states ----------------
__global__ void init_kernel() {
    int i = blockIdx.x * blockDim.x + threadIdx.x;
    if (i < NN * BB * HH) {
        g_h0[0][i] = 0.f;
        g_h1[0][i] = 0.f;
        g_c0[i] = 0.f;
        g_c1[i] = 0.f;
    }
}

// ---------------- input layer: z = lrelu(x @ Win^T + bin, 0.2) * 10 ----------------
// grid: 2048 blocks x 256 threads; each block handles 8 tokens x 512 cols
__global__ void __launch_bounds__(256) input_kernel(const float* __restrict__ x,
                                                    const float* __restrict__ Win,
                                                    const float* __restrict__ binp) {
    int tok0 = blockIdx.x * 8;
    int tid = threadIdx.x;
    __shared__ float xs[8][DIN];
    for (int i = tid; i < 8 * DIN; i += 256) {
        xs[i >> 6][i & 63] = x[(size_t)tok0 * DIN + i];
    }
    __syncthreads();
    int c0 = tid, c1 = tid + 256;
    float a0[8], a1[8];
#pragma unroll
    for (int k = 0; k < 8; k++) { a0[k] = 0.f; a1[k] = 0.f; }
    const float* w0 = Win + (size_t)c0 * DIN;
    const float* w1 = Win + (size_t)c1 * DIN;
    for (int k = 0; k < DIN; k++) {
        float wv0 = w0[k], wv1 = w1[k];
#pragma unroll
        for (int tk = 0; tk < 8; tk++) {
            a0[tk] += wv0 * xs[tk][k];
            a1[tk] += wv1 * xs[tk][k];
        }
    }
    float bb0 = binp[c0], bb1 = binp[c1];
#pragma unroll
    for (int tk = 0; tk < 8; tk++) {
        float v0 = a0[tk] + bb0;
        v0 = (v0 > 0.f ? v0 : 0.2f * v0) * 10.0f;
        g_z[(size_t)(tok0 + tk) * HH + c0] = v0;
        float v1 = a1[tk] + bb1;
        v1 = (v1 > 0.f ? v1 : 0.2f * v1) * 10.0f;
        g_z[(size_t)(tok0 + tk) * HH + c1] = v1;
    }
}

// ---------------- LSTM cell kernel (one per layer per timestep) ----------------
// L1=0: gates = z_t @ W_ih0^T + h0_prev @ W_hh0^T + (b_ih0+b_hh0)
// L1=1: gates = h0_cur @ W_ih1^T + h1_prev @ W_hh1^T + (b_ih1+b_hh1)
// Block: ensemble n = blockIdx.y, j-tile j0 = blockIdx.x*32; computes 64 rows (b) x 128 cols
// where cols = 4 gate-strips (i,f,g,o) x 32 contiguous j, GEMM K=1024 (concat).
template <int L1>
__global__ void __launch_bounds__(256) cell_kernel(const float* __restrict__ W0,
                                                   const float* __restrict__ W1,
                                                   const float* __restrict__ ba,
                                                   const float* __restrict__ bb,
                                                   int t) {
    const int n = blockIdx.y;
    const int j0 = blockIdx.x * 32;
    const int tid = threadIdx.x;

    __shared__ float As[16][64];
    __shared__ float Bs[16][132];
    __shared__ float gsm[64][132];
    __shared__ float bias_s[128];

    const int pp = t & 1, pc = (t + 1) & 1;
    const float* h0p = g_h0[pp];
    const float* h0c = g_h0[pc];
    const float* h1p = g_h1[pp];

    if (tid < 128) {
        int wr = (tid >> 5) * HH + j0 + (tid & 31);
        bias_s[tid] = ba[n * 4 * HH + wr] + bb[n * 4 * HH + wr];
    }

    const int ar = tid >> 2, ak4 = (tid & 3) * 4;       // A loader: row, k-quad
    const int bc = tid >> 1, bk4 = (tid & 1) * 8;       // B loader: col, k-start
    const int bwr = (bc >> 5) * HH + j0 + (bc & 31);    // weight row for col bc
    const int tx = tid & 15, ty = tid >> 4;

    float acc[4][8];
#pragma unroll
    for (int i = 0; i < 4; i++)
#pragma unroll
        for (int j = 0; j < 8; j++) acc[i][j] = 0.f;

    float4 pa, pb0, pb1;
    auto fetch = [&](int k0) {
        int kl = k0 & (HH - 1);
        const float* Arow;
        const float* W;
        if (k0 < HH) {
            W = W0;
            if (L1) Arow = h0c + (n * BB + ar) * HH;
            else    Arow = g_z + (size_t)(ar * TT + t) * HH;
        } else {
            W = W1;
            if (L1) Arow = h1p + (n * BB + ar) * HH;
            else    Arow = h0p + (n * BB + ar) * HH;
        }
        pa = *(const float4*)(Arow + kl + ak4);
        const float* wrow = W + ((size_t)n * 4 * HH + bwr) * HH + kl;
        pb0 = *(const float4*)(wrow + bk4);
        pb1 = *(const float4*)(wrow + bk4 + 4);
    };

    fetch(0);
#pragma unroll 1
    for (int it = 0; it < 64; ++it) {
        As[ak4 + 0][ar] = pa.x;
        As[ak4 + 1][ar] = pa.y;
        As[ak4 + 2][ar] = pa.z;
        As[ak4 + 3][ar] = pa.w;
        Bs[bk4 + 0][bc] = pb0.x;
        Bs[bk4 + 1][bc] = pb0.y;
        Bs[bk4 + 2][bc] = pb0.z;
        Bs[bk4 + 3][bc] = pb0.w;
        Bs[bk4 + 4][bc] = pb1.x;
        Bs[bk4 + 5][bc] = pb1.y;
        Bs[bk4 + 6][bc] = pb1.z;
        Bs[bk4 + 7][bc] = pb1.w;
        __syncthreads();
        if (it < 63) fetch((it + 1) * 16);
#pragma unroll
        for (int kk = 0; kk < 16; ++kk) {
            float4 a4 = *(const float4*)&As[kk][ty * 4];
            float4 b0 = *(const float4*)&Bs[kk][tx * 8];
            float4 b1 = *(const float4*)&Bs[kk][tx * 8 + 4];
            float av[4] = {a4.x, a4.y, a4.z, a4.w};
            float bv[8] = {b0.x, b0.y, b0.z, b0.w, b1.x, b1.y, b1.z, b1.w};
#pragma unroll
            for (int i = 0; i < 4; i++)
#pragma unroll
                for (int j = 0; j < 8; j++) acc[i][j] += av[i] * bv[j];
        }
        __syncthreads();
    }

    // gate tile -> smem (+bias), then cell update
#pragma unroll
    for (int i = 0; i < 4; i++)
#pragma unroll
        for (int j = 0; j < 8; j++)
            gsm[ty * 4 + i][tx * 8 + j] = acc[i][j] + bias_s[tx * 8 + j];
    __syncthreads();

    float* C = L1 ? g_c1 : g_c0;
    float* Hn = L1 ? g_h1[pc] : g_h0[pc];
    for (int p = tid; p < BB * 32; p += 256) {
        int b = p >> 5, jj = p & 31;
        float gi = gsm[b][jj];
        float gf = gsm[b][32 + jj];
        float gg = gsm[b][64 + jj];
        float go = gsm[b][96 + jj];
        int sidx = (n * BB + b) * HH + j0 + jj;
        float cn = sigf(gf) * C[sidx] + sigf(gi) * tanhf(gg);
        float hn = sigf(go) * tanhf(cn);
        C[sidx] = cn;
        Hn[sidx] = hn;
        if (L1) g_y[((size_t)(n * BB + b) * TT + t) * HH + j0 + jj] = hn;
    }
}

// ---------------- fused head: out = lrelu(y @ Wh1^T + bh1) @ Wh2^T + bh2 ----------------
// grid (256 row-tiles, 8 ensembles); block handles 64 rows (one b, 64 consecutive t)
// loops over 4 m-chunks of 128, accumulating the O=7 outputs in registers.
__global__ void __launch_bounds__(256) head_kernel(const float* __restrict__ Wh1,
                                                   const float* __restrict__ bh1,
                                                   const float* __restrict__ Wh2,
                                                   const float* __restrict__ bh2,
                                                   float* __restrict__ out) {
    const int n = blockIdx.y;
    const int rt = blockIdx.x;    // 0..255
    const int b = rt >> 2;
    const int t0 = (rt & 3) * 64;
    const int tid = threadIdx.x;

    __shared__ float As[16][64];
    __shared__ float Bs[16][132];
    __shared__ float hsm[64][132];

    const float* Abase = g_y + ((size_t)(n * BB + b) * TT + t0) * HH;
    const int ar = tid >> 2, ak4 = (tid & 3) * 4;
    const int bc = tid >> 1, bk4 = (tid & 1) * 8;
    const int tx = tid & 15, ty = tid >> 4;

    float o0 = 0.f, o1 = 0.f;
    const int p0 = tid * 2, p1 = tid * 2 + 1;
    const int r0 = p0 / 7, q0 = p0 % 7;
    const int r1 = p1 / 7, q1 = p1 % 7;
    const bool act = (p0 < 64 * OO);

    for (int mt = 0; mt < 4; ++mt) {
        const int m0 = mt * 128;
        float acc[4][8];
#pragma unroll
        for (int i = 0; i < 4; i++)
#pragma unroll
            for (int j = 0; j < 8; j++) acc[i][j] = 0.f;

        float4 pa, pb0, pb1;
        auto fetch = [&](int k0) {
            pa = *(const float4*)(Abase + (size_t)ar * HH + k0 + ak4);
            const float* wrow = Wh1 + ((size_t)(n * MMd + m0 + bc)) * HH + k0;
            pb0 = *(const float4*)(wrow + bk4);
            pb1 = *(const float4*)(wrow + bk4 + 4);
        };
        fetch(0);
#pragma unroll 1
        for (int it = 0; it < 32; ++it) {
            As[ak4 + 0][ar] = pa.x;
            As[ak4 + 1][ar] = pa.y;
            As[ak4 + 2][ar] = pa.z;
            As[ak4 + 3][ar] = pa.w;
            Bs[bk4 + 0][bc] = pb0.x;
            Bs[bk4 + 1][bc] = pb0.y;
            Bs[bk4 + 2][bc] = pb0.z;
            Bs[bk4 + 3][bc] = pb0.w;
            Bs[bk4 + 4][bc] = pb1.x;
            Bs[bk4 + 5][bc] = pb1.y;
            Bs[bk4 + 6][bc] = pb1.z;
            Bs[bk4 + 7][bc] = pb1.w;
            __syncthreads();
            if (it < 31) fetch((it + 1) * 16);
#pragma unroll
            for (int kk = 0; kk < 16; ++kk) {
                float4 a4 = *(const float4*)&As[kk][ty * 4];
                float4 b0v = *(const float4*)&Bs[kk][tx * 8];
                float4 b1v = *(const float4*)&Bs[kk][tx * 8 + 4];
                float av[4] = {a4.x, a4.y, a4.z, a4.w};
                float bv[8] = {b0v.x, b0v.y, b0v.z, b0v.w, b1v.x, b1v.y, b1v.z, b1v.w};
#pragma unroll
                for (int i = 0; i < 4; i++)
#pragma unroll
                    for (int j = 0; j < 8; j++) acc[i][j] += av[i] * bv[j];
            }
            __syncthreads();
        }
        // hidden tile with LeakyReLU(0.2)
#pragma unroll
        for (int i = 0; i < 4; i++)
#pragma unroll
            for (int j = 0; j < 8; j++) {
                float v = acc[i][j] + bh1[n * MMd + m0 + tx * 8 + j];
                hsm[ty * 4 + i][tx * 8 + j] = (v > 0.f ? v : 0.2f * v);
            }
        __syncthreads();
        if (act) {
            const float* w2a = Wh2 + (size_t)(n * OO + q0) * MMd + m0;
            const float* w2b = Wh2 + (size_t)(n * OO + q1) * MMd + m0;
            float s0 = 0.f, s1 = 0.f;
            for (int mm = 0; mm < 128; ++mm) {
                s0 += hsm[r0][mm] * w2a[mm];
                s1 += hsm[r1][mm] * w2b[mm];
            }
            o0 += s0;
            o1 += s1;
        }
        __syncthreads();
    }
    if (act) {
        out[((size_t)(n * BB + b) * TT + (t0 + r0)) * OO + q0] = o0 + bh2[n * OO + q0];
        out[((size_t)(n * BB + b) * TT + (t0 + r1)) * OO + q1] = o1 + bh2[n * OO + q1];
    }
}

// ---------------- launch ----------------
extern "C" void kernel_launch(void* const* d_in, const int* in_sizes, int n_in,
                              void* d_out, int out_size) {
    const float* x     = (const float*)d_in[0];
    const float* Win   = (const float*)d_in[1];
    const float* binp  = (const float*)d_in[2];
    const float* W_ih0 = (const float*)d_in[3];
    const float* W_hh0 = (const float*)d_in[4];
    const float* b_ih0 = (const float*)d_in[5];
    const float* b_hh0 = (const float*)d_in[6];
    const float* W_ih1 = (const float*)d_in[7];
    const float* W_hh1 = (const float*)d_in[8];
    const float* b_ih1 = (const float*)d_in[9];
    const float* b_hh1 = (const float*)d_in[10];
    const float* Wh1   = (const float*)d_in[11];
    const float* bh1   = (const float*)d_in[12];
    const float* Wh2   = (const float*)d_in[13];
    const float* bh2   = (const float*)d_in[14];
    float* out = (float*)d_out;

    init_kernel<<<(NN * BB * HH + 255) / 256, 256>>>();
    input_kernel<<<(BB * TT) / 8, 256>>>(x, Win, binp);

    dim3 cgrid(HH / 32, NN);  // 16 x 8 = 128 blocks
    for (int t = 0; t < TT; ++t) {
        cell_kernel<0><<<cgrid, 256>>>(W_ih0, W_hh0, b_ih0, b_hh0, t);
        cell_kernel<1><<<cgrid, 256>>>(W_ih1, W_hh1, b_ih1, b_hh1, t);
    }

    head_kernel<<<dim3(256, NN), 256>>>(Wh1, bh1, Wh2, bh2, out);
}

// round 3
// speedup vs baseline: 5.7229x; 5.7229x over previous
#include <cuda_runtime.h>
#include <cuda_fp16.h>
#include <math.h>
#include <cstdint>

#define NN 8
#define BB 64
#define TT 256
#define DIN 64
#define HH 512
#define MMd 512
#define OO 7

// ---------------- device globals (no allocation allowed) ----------------
__device__ __half g_z[BB * TT * HH];                 // input-layer output, fp16, [b][t][H]
__device__ __half g_h0[2][NN * BB * HH];             // double-buffered hidden, fp16
__device__ __half g_h1[2][NN * BB * HH];
__device__ float  g_c0[NN * BB * HH];                // cell states fp32
__device__ float  g_c1[NN * BB * HH];
__device__ __half g_y[(size_t)NN * BB * TT * HH];    // layer-1 outputs, fp16
__device__ __half g_wih0[NN * 4 * HH * HH];          // fp16 weight copies
__device__ __half g_whh0[NN * 4 * HH * HH];
__device__ __half g_wih1[NN * 4 * HH * HH];
__device__ __half g_whh1[NN * 4 * HH * HH];
__device__ __half g_wh1h[NN * MMd * HH];             // head Wh1 fp16

__device__ __forceinline__ float sigf(float x) { return 1.0f / (1.0f + expf(-x)); }

#define SW128(x) ((x) ^ (((x) >> 3) & 0x70))

__device__ __forceinline__ uint32_t smem_u32(const void* p) {
    uint32_t a;
    asm("{ .reg .u64 t; cvta.to.shared.u64 t, %1; cvt.u32.u64 %0, t; }" : "=r"(a) : "l"(p));
    return a;
}

__device__ __forceinline__ void ldsm4(uint32_t* r, uint32_t addr) {
    asm volatile("ldmatrix.sync.aligned.m8n8.x4.shared.b16 {%0,%1,%2,%3}, [%4];"
                 : "=r"(r[0]), "=r"(r[1]), "=r"(r[2]), "=r"(r[3]) : "r"(addr));
}

__device__ __forceinline__ void hmma(float* d, const uint32_t* a, const uint32_t* b) {
    asm volatile(
        "mma.sync.aligned.m16n8k16.row.col.f32.f16.f16.f32 "
        "{%0,%1,%2,%3}, {%4,%5,%6,%7}, {%8,%9}, {%0,%1,%2,%3};"
        : "+f"(d[0]), "+f"(d[1]), "+f"(d[2]), "+f"(d[3])
        : "r"(a[0]), "r"(a[1]), "r"(a[2]), "r"(a[3]), "r"(b[0]), "r"(b[1]));
}

// ---------------- init: zero initial states ----------------
__global__ void init_kernel() {
    int i = blockIdx.x * blockDim.x + threadIdx.x;
    if (i < NN * BB * HH) {
        g_h0[0][i] = __float2half(0.f);
        g_h1[0][i] = __float2half(0.f);
        g_c0[i] = 0.f;
        g_c1[i] = 0.f;
    }
}

// ---------------- weight fp32 -> fp16 conversion ----------------
__global__ void __launch_bounds__(256) f2h_kernel(const float4* __restrict__ src, int which, int n4) {
    int i = blockIdx.x * 256 + threadIdx.x;
    if (i >= n4) return;
    __half2* dst = which == 0 ? (__half2*)g_wih0 :
                   which == 1 ? (__half2*)g_whh0 :
                   which == 2 ? (__half2*)g_wih1 :
                   which == 3 ? (__half2*)g_whh1 : (__half2*)g_wh1h;
    float4 v = src[i];
    dst[2 * i]     = __floats2half2_rn(v.x, v.y);
    dst[2 * i + 1] = __floats2half2_rn(v.z, v.w);
}

// ---------------- input layer: z = lrelu(x @ Win^T + bin, 0.2) * 10 (fp16 out) ----------------
__global__ void __launch_bounds__(256) input_kernel(const float* __restrict__ x,
                                                    const float* __restrict__ Win,
                                                    const float* __restrict__ binp) {
    int tok0 = blockIdx.x * 8;
    int tid = threadIdx.x;
    __shared__ float xs[8][DIN];
    for (int i = tid; i < 8 * DIN; i += 256) xs[i >> 6][i & 63] = x[(size_t)tok0 * DIN + i];
    __syncthreads();
    int c0 = tid, c1 = tid + 256;
    float a0[8], a1[8];
#pragma unroll
    for (int k = 0; k < 8; k++) { a0[k] = 0.f; a1[k] = 0.f; }
    const float* w0 = Win + (size_t)c0 * DIN;
    const float* w1 = Win + (size_t)c1 * DIN;
    for (int k = 0; k < DIN; k++) {
        float wv0 = w0[k], wv1 = w1[k];
#pragma unroll
        for (int tk = 0; tk < 8; tk++) {
            a0[tk] += wv0 * xs[tk][k];
            a1[tk] += wv1 * xs[tk][k];
        }
    }
    float bb0 = binp[c0], bb1 = binp[c1];
#pragma unroll
    for (int tk = 0; tk < 8; tk++) {
        float v0 = a0[tk] + bb0;
        v0 = (v0 > 0.f ? v0 : 0.2f * v0) * 10.0f;
        g_z[(size_t)(tok0 + tk) * HH + c0] = __float2half(v0);
        float v1 = a1[tk] + bb1;
        v1 = (v1 > 0.f ? v1 : 0.2f * v1) * 10.0f;
        g_z[(size_t)(tok0 + tk) * HH + c1] = __float2half(v1);
    }
}

// ---------------- HMMA LSTM cell kernel ----------------
// CTA (jt, n): D[128 x 64] = A[128 x 1024] . B[64 x 1024]^T (both K-major fp16)
//   A rows m: gate = m>>5, j = jt*32 + (m&31); B rows: batch b.
// SMEM (dyn 49152): A stages @0/16384 (16KB), B stages @32768/40960 (8KB).
// Epilogue gsm float[128][65] overlays @0.
template <int L1>
__global__ void __launch_bounds__(256) cell_mma(const float* __restrict__ ba,
                                                const float* __restrict__ bb,
                                                int t) {
    extern __shared__ char smem[];
    const int n = blockIdx.y, jt = blockIdx.x, tid = threadIdx.x;
    const int wid = tid >> 5, l = tid & 31;
    uint32_t sbase = smem_u32(smem);

    const int pp = t & 1, pc = (t + 1) & 1;
    const __half* h0p = g_h0[pp];
    const __half* h0c = g_h0[pc];
    const __half* h1p = g_h1[pp];

    // ---- global -> smem loader mappings ----
    const int am = tid >> 1, akw = (tid & 1) * 4;         // A: row, 4 x 16B units
    const int grow = (am >> 5) * HH + jt * 32 + (am & 31);
    const __half* Wi = (L1 ? g_wih1 : g_wih0) + ((size_t)n * 4 * HH + grow) * HH;
    const __half* Wh = (L1 ? g_whh1 : g_whh0) + ((size_t)n * 4 * HH + grow) * HH;
    uint32_t a_sts[4];
#pragma unroll
    for (int i = 0; i < 4; i++) a_sts[i] = SW128((uint32_t)(am * 128 + (akw + i) * 16));

    const int bm = tid >> 2, bkw = (tid & 3) * 2;         // B: row, 2 x 16B units
    const __half* BsrcLo = L1 ? (h0c + (n * BB + bm) * HH)
                              : (g_z + ((size_t)bm * TT + t) * HH);
    const __half* BsrcHi = L1 ? (h1p + (n * BB + bm) * HH)
                              : (h0p + (n * BB + bm) * HH);
    uint32_t b_sts[2];
#pragma unroll
    for (int i = 0; i < 2; i++) b_sts[i] = SW128((uint32_t)(bm * 128 + (bkw + i) * 16));

    uint4 ra[4], rb[2];
    auto fetch = [&](int c) {
        const __half* wsrc = (c < 8) ? (Wi + c * 64) : (Wh + (c - 8) * 64);
#pragma unroll
        for (int i = 0; i < 4; i++) ra[i] = *(const uint4*)(wsrc + (akw + i) * 8);
        const __half* bs = (c < 8) ? (BsrcLo + c * 64) : (BsrcHi + (c - 8) * 64);
#pragma unroll
        for (int i = 0; i < 2; i++) rb[i] = *(const uint4*)(bs + (bkw + i) * 8);
    };
    auto store_stage = [&](int s) {
        char* Ab = smem + s * 16384;
        char* Bb = smem + 32768 + s * 8192;
#pragma unroll
        for (int i = 0; i < 4; i++) *(uint4*)(Ab + a_sts[i]) = ra[i];
#pragma unroll
        for (int i = 0; i < 2; i++) *(uint4*)(Bb + b_sts[i]) = rb[i];
    };

    // ---- mma fragment mappings ----
    const int arow = wid * 16 + (l & 7) + ((l >> 3) & 1) * 8;
    const uint32_t a_rb = (uint32_t)arow * 128u;
    const uint32_t a_swz = (uint32_t)((arow & 7) << 4);
    const uint32_t akbx = (uint32_t)(((l >> 4) & 1) * 16);
    const int brb = (l & 7) + ((l >> 4) & 1) * 8;
    const uint32_t bkbx = (uint32_t)(((l >> 3) & 1) * 16);

    float acc[8][4];
#pragma unroll
    for (int i = 0; i < 8; i++)
#pragma unroll
        for (int j = 0; j < 4; j++) acc[i][j] = 0.f;

    auto compute = [&](int s) {
        uint32_t Ab = sbase + s * 16384;
        uint32_t Bb = sbase + 32768 + s * 8192;
#pragma unroll
        for (int ks = 0; ks < 4; ++ks) {
            uint32_t a[4];
            ldsm4(a, Ab + a_rb + (((uint32_t)(ks * 32) + akbx) ^ a_swz));
            uint32_t bfr[16];
#pragma unroll
            for (int p = 0; p < 4; ++p) {
                int br = p * 16 + brb;
                ldsm4(&bfr[p * 4],
                      Bb + (uint32_t)br * 128 + (((uint32_t)(ks * 32) + bkbx) ^ (uint32_t)((br & 7) << 4)));
            }
#pragma unroll
            for (int nt = 0; nt < 8; ++nt) hmma(acc[nt], a, &bfr[nt * 2]);
        }
    };

    // ---- pipelined mainloop: 16 K-chunks of 64 ----
    fetch(0);
    store_stage(0);
    fetch(1);
    __syncthreads();
#pragma unroll 1
    for (int c = 0; c < 16; ++c) {
        if (c < 15) store_stage((c + 1) & 1);
        if (c < 14) fetch(c + 2);
        compute(c & 1);
        __syncthreads();
    }

    // ---- epilogue: regs -> gsm -> LSTM cell update ----
    float* gsm = (float*)smem;   // [128][65]
    {
        int r0r = wid * 16 + (l >> 2);
        int cc = (l & 3) * 2;
#pragma unroll
        for (int nt = 0; nt < 8; ++nt) {
            int col = nt * 8 + cc;
            gsm[r0r * 65 + col]           = acc[nt][0];
            gsm[r0r * 65 + col + 1]       = acc[nt][1];
            gsm[(r0r + 8) * 65 + col]     = acc[nt][2];
            gsm[(r0r + 8) * 65 + col + 1] = acc[nt][3];
        }
    }
    __syncthreads();

    float* C = L1 ? g_c1 : g_c0;
    __half* Hn = L1 ? g_h1[pc] : g_h0[pc];
    const float* baN = ba + n * 4 * HH;
    const float* bbN = bb + n * 4 * HH;
#pragma unroll 1
    for (int p = tid; p < BB * 32; p += 256) {
        int b = p >> 5, jj = p & 31;
        int jcol = jt * 32 + jj;
        float gi = gsm[(jj) * 65 + b]      + baN[jcol]          + bbN[jcol];
        float gf = gsm[(32 + jj) * 65 + b] + baN[HH + jcol]     + bbN[HH + jcol];
        float gg = gsm[(64 + jj) * 65 + b] + baN[2 * HH + jcol] + bbN[2 * HH + jcol];
        float go = gsm[(96 + jj) * 65 + b] + baN[3 * HH + jcol] + bbN[3 * HH + jcol];
        int sidx = (n * BB + b) * HH + jcol;
        float cn = sigf(gf) * C[sidx] + sigf(gi) * tanhf(gg);
        float hn = sigf(go) * tanhf(cn);
        C[sidx] = cn;
        Hn[sidx] = __float2half(hn);
        if (L1) g_y[((size_t)(n * BB + b) * TT + t) * HH + jcol] = __float2half(hn);
    }
}

// ---------------- fused head (HMMA stage-1, fp32 stage-2) ----------------
// CTA (rt, n): 64 tokens (b, t0..t0+63); loop over 4 m-chunks of 128.
// GEMM: D[64 tok x 128 m] = y[64 x 64k] . Wh1[128 x 64k]^T, K chunks of 64 (8 per m-chunk).
// SMEM (dyn 49152): A(y) stages @0/8192 (8KB), B(Wh1) stages @16384/32768 (16KB).
// hsm float[64][132] overlays @0.
__global__ void __launch_bounds__(256) head_kernel(const float* __restrict__ bh1,
                                                   const float* __restrict__ Wh2,
                                                   const float* __restrict__ bh2,
                                                   float* __restrict__ out) {
    extern __shared__ char smem[];
    const int n = blockIdx.y;
    const int rt = blockIdx.x;
    const int b = rt >> 2;
    const int t0 = (rt & 3) * 64;
    const int tid = threadIdx.x;
    const int wid = tid >> 5, l = tid & 31;
    const int wm = wid & 3, wn = wid >> 2;
    uint32_t sbase = smem_u32(smem);

    // loaders
    const int am = tid >> 2, akw = (tid & 3) * 2;         // A: 64 rows x 2 units
    const __half* ybase = g_y + ((size_t)((n * BB + b) * TT) + t0 + am) * HH;
    uint32_t a_sts[2];
#pragma unroll
    for (int i = 0; i < 2; i++) a_sts[i] = SW128((uint32_t)(am * 128 + (akw + i) * 16));
    const int bmr = tid >> 1, bkw = (tid & 1) * 4;        // B: 128 rows x 4 units
    uint32_t b_sts[4];
#pragma unroll
    for (int i = 0; i < 4; i++) b_sts[i] = SW128((uint32_t)(bmr * 128 + (bkw + i) * 16));

    // fragment mappings
    const int arow = wm * 16 + (l & 7) + ((l >> 3) & 1) * 8;
    const uint32_t a_rb = (uint32_t)arow * 128u;
    const uint32_t a_swz = (uint32_t)((arow & 7) << 4);
    const uint32_t akbx = (uint32_t)(((l >> 4) & 1) * 16);
    const int brb = (l & 7) + ((l >> 4) & 1) * 8;
    const uint32_t bkbx = (uint32_t)(((l >> 3) & 1) * 16);

    float o0 = 0.f, o1 = 0.f;
    const int p0 = tid * 2, p1 = tid * 2 + 1;
    const int r0 = p0 / 7, q0 = p0 % 7;
    const int r1 = p1 / 7, q1 = p1 % 7;
    const bool act = (p0 < 64 * OO);

    float* hsm = (float*)smem;   // [64][132]

#pragma unroll 1
    for (int mt = 0; mt < 4; ++mt) {
        const int m0 = mt * 128;
        const __half* wbase = g_wh1h + ((size_t)(n * MMd) + m0 + bmr) * HH;

        uint4 ra[2], rb[4];
        auto fetch = [&](int kc) {
#pragma unroll
            for (int i = 0; i < 2; i++) ra[i] = *(const uint4*)(ybase + kc * 64 + (akw + i) * 8);
#pragma unroll
            for (int i = 0; i < 4; i++) rb[i] = *(const uint4*)(wbase + kc * 64 + (bkw + i) * 8);
        };
        auto store_stage = [&](int s) {
            char* Ab = smem + s * 8192;
            char* Bb = smem + 16384 + s * 16384;
#pragma unroll
            for (int i = 0; i < 2; i++) *(uint4*)(Ab + a_sts[i]) = ra[i];
#pragma unroll
            for (int i = 0; i < 4; i++) *(uint4*)(Bb + b_sts[i]) = rb[i];
        };

        float acc[8][4];
#pragma unroll
        for (int i = 0; i < 8; i++)
#pragma unroll
            for (int j = 0; j < 4; j++) acc[i][j] = 0.f;

        auto compute = [&](int s) {
            uint32_t Ab = sbase + s * 8192;
            uint32_t Bb = sbase + 16384 + s * 16384;
#pragma unroll
            for (int ks = 0; ks < 4; ++ks) {
                uint32_t a[4];
                ldsm4(a, Ab + a_rb + (((uint32_t)(ks * 32) + akbx) ^ a_swz));
                uint32_t bfr[16];
#pragma unroll
                for (int p = 0; p < 4; ++p) {
                    int br = wn * 64 + p * 16 + brb;
                    ldsm4(&bfr[p * 4],
                          Bb + (uint32_t)br * 128 + (((uint32_t)(ks * 32) + bkbx) ^ (uint32_t)((br & 7) << 4)));
                }
#pragma unroll
                for (int nt = 0; nt < 8; ++nt) hmma(acc[nt], a, &bfr[nt * 2]);
            }
        };

        fetch(0);
        store_stage(0);
        fetch(1);
        __syncthreads();
#pragma unroll 1
        for (int kc = 0; kc < 8; ++kc) {
            if (kc < 7) store_stage((kc + 1) & 1);
            if (kc < 6) fetch(kc + 2);
            compute(kc & 1);
            __syncthreads();
        }

        // bias + LeakyReLU -> hsm
        {
            int r = wm * 16 + (l >> 2);
            int cc = (l & 3) * 2;
#pragma unroll
            for (int nt = 0; nt < 8; ++nt) {
                int col = wn * 64 + nt * 8 + cc;
                float bia = bh1[n * MMd + m0 + col];
                float bib = bh1[n * MMd + m0 + col + 1];
                float v0 = acc[nt][0] + bia, v1 = acc[nt][1] + bib;
                float v2 = acc[nt][2] + bia, v3 = acc[nt][3] + bib;
                hsm[r * 132 + col]           = (v0 > 0.f ? v0 : 0.2f * v0);
                hsm[r * 132 + col + 1]       = (v1 > 0.f ? v1 : 0.2f * v1);
                hsm[(r + 8) * 132 + col]     = (v2 > 0.f ? v2 : 0.2f * v2);
                hsm[(r + 8) * 132 + col + 1] = (v3 > 0.f ? v3 : 0.2f * v3);
            }
        }
        __syncthreads();
        if (act) {
            const float* w2a = Wh2 + (size_t)(n * OO + q0) * MMd + m0;
            const float* w2b = Wh2 + (size_t)(n * OO + q1) * MMd + m0;
            float s0 = 0.f, s1 = 0.f;
#pragma unroll 4
            for (int mm = 0; mm < 128; ++mm) {
                s0 += hsm[r0 * 132 + mm] * w2a[mm];
                s1 += hsm[r1 * 132 + mm] * w2b[mm];
            }
            o0 += s0;
            o1 += s1;
        }
        __syncthreads();
    }
    if (act) {
        out[((size_t)(n * BB + b) * TT + (t0 + r0)) * OO + q0] = o0 + bh2[n * OO + q0];
        out[((size_t)(n * BB + b) * TT + (t0 + r1)) * OO + q1] = o1 + bh2[n * OO + q1];
    }
}

// ---------------- launch ----------------
extern "C" void kernel_launch(void* const* d_in, const int* in_sizes, int n_in,
                              void* d_out, int out_size) {
    const float* x     = (const float*)d_in[0];
    const float* Win   = (const float*)d_in[1];
    const float* binp  = (const float*)d_in[2];
    const float* W_ih0 = (const float*)d_in[3];
    const float* W_hh0 = (const float*)d_in[4];
    const float* b_ih0 = (const float*)d_in[5];
    const float* b_hh0 = (const float*)d_in[6];
    const float* W_ih1 = (const float*)d_in[7];
    const float* W_hh1 = (const float*)d_in[8];
    const float* b_ih1 = (const float*)d_in[9];
    const float* b_hh1 = (const float*)d_in[10];
    const float* Wh1   = (const float*)d_in[11];
    const float* bh1   = (const float*)d_in[12];
    const float* Wh2   = (const float*)d_in[13];
    const float* bh2   = (const float*)d_in[14];
    float* out = (float*)d_out;

    init_kernel<<<(NN * BB * HH + 255) / 256, 256>>>();
    input_kernel<<<(BB * TT) / 8, 256>>>(x, Win, binp);

    const int n4 = NN * 4 * HH * HH / 4;
    f2h_kernel<<<(n4 + 255) / 256, 256>>>((const float4*)W_ih0, 0, n4);
    f2h_kernel<<<(n4 + 255) / 256, 256>>>((const float4*)W_hh0, 1, n4);
    f2h_kernel<<<(n4 + 255) / 256, 256>>>((const float4*)W_ih1, 2, n4);
    f2h_kernel<<<(n4 + 255) / 256, 256>>>((const float4*)W_hh1, 3, n4);
    const int n4h = NN * MMd * HH / 4;
    f2h_kernel<<<(n4h + 255) / 256, 256>>>((const float4*)Wh1, 4, n4h);

    dim3 cgrid(HH / 32, NN);  // 16 x 8 = 128 CTAs
    for (int t = 0; t < TT; ++t) {
        cell_mma<0><<<cgrid, 256, 49152>>>(b_ih0, b_hh0, t);
        cell_mma<1><<<cgrid, 256, 49152>>>(b_ih1, b_hh1, t);
    }

    head_kernel<<<dim3(256, NN), 256, 49152>>>(bh1, Wh2, bh2, out);
}